// round 3
// baseline (speedup 1.0000x reference)
#include <cuda_runtime.h>
#include <cstdint>

// Problem constants (shapes fixed by the dataset).
#define N_GT          128
#define CHUNK         64        // anchors per warp
#define WARPS_PER_BLK 8
#define THREADS       256
#define MAX_WARPS     4096      // 262144 / 64

__device__ unsigned long long g_scratch[MAX_WARPS * N_GT]; // [warp][gt] packed keys

// Fused kernel: row threshold flag (-1/-2) + per-warp column argmax candidates.
// Warp owns CHUNK contiguous anchors; lane l tracks gts {l, l+32, l+64, l+96}.
// All IoU orderings replicated at fp32-rounded-quotient exactness:
//   hot loop uses margin-certified cross-multiplication, rare ambiguous band
//   falls back to IEEE __fdiv_rn (matches jnp's fp32 inter/union exactly).
__global__ __launch_bounds__(THREADS) void assign_main(
    const float4* __restrict__ anchor,
    const float4* __restrict__ gt,
    float* __restrict__ assign)
{
    __shared__ float4 s_anchor[WARPS_PER_BLK][CHUNK];
    __shared__ float s_gx1[N_GT], s_gy1[N_GT], s_gx2[N_GT], s_gy2[N_GT], s_ga[N_GT];

    const int tid  = threadIdx.x;
    const int lane = tid & 31;
    const int wid  = tid >> 5;
    const int gwarp = blockIdx.x * WARPS_PER_BLK + wid;
    const int base  = gwarp * CHUNK;

    if (tid < N_GT) {
        float4 g = gt[tid];
        s_gx1[tid] = g.x; s_gy1[tid] = g.y;
        s_gx2[tid] = g.z; s_gy2[tid] = g.w;
        s_ga[tid]  = (g.z - g.x) * (g.w - g.y);
    }
    #pragma unroll
    for (int r = 0; r < CHUNK / 32; ++r)
        s_anchor[wid][r * 32 + lane] = anchor[base + r * 32 + lane];
    __syncthreads();

    float gx1[4], gy1[4], gx2[4], gy2[4], ga[4];
    float bi[4], bu[4];     // running best inter / union for this lane's 4 gts
    int   bidx[4];
    #pragma unroll
    for (int g = 0; g < 4; ++g) {
        int j = lane + 32 * g;
        gx1[g] = s_gx1[j]; gy1[g] = s_gy1[j];
        gx2[g] = s_gx2[j]; gy2[g] = s_gy2[j];
        ga[g]  = s_ga[j];
        bi[g] = 0.0f; bu[g] = 1.0f; bidx[g] = base;  // iou 0, lowest idx in chunk
    }

    const float c    = 0.3f;      // THRESH as fp32 (matches jax f32 compare)
    const float REL  = 4e-6f;     // certainty margin, ~32+ fp32 ulps of the quotient
    const float CROW = REL * 0.3f;
    float myres = -1.0f;

    for (int t = 0; t < CHUNK; ++t) {
        float4 a = s_anchor[wid][t];                  // LDS.128 broadcast
        float areaA = (a.z - a.x) * (a.w - a.y);
        bool hit = false;

        #pragma unroll
        for (int g = 0; g < 4; ++g) {
            float w     = fminf(a.z, gx2[g]) - fmaxf(a.x, gx1[g]);
            float h     = fminf(a.w, gy2[g]) - fmaxf(a.y, gy1[g]);
            bool  pos   = fminf(w, h) > 0.0f;
            float inter = w * h;
            float u     = (areaA + ga[g]) - inter;

            // Row: rounded(inter/u) >= 0.3f ?  certain band via inter - 0.3u
            float t1   = fmaf(-c, u, inter);
            float thr2 = CROW * u;
            hit = hit || (pos && (t1 > thr2));

            // Column: rounded(q_new) > rounded(q_best) ? (first-wins on equal)
            float biu = bi[g] * u;
            float d   = fmaf(inter, bu[g], -biu);
            float thr = REL * biu;
            bool better  = pos && (d > thr);
            bool amb_any = pos && ((fabsf(d) <= thr) || (fabsf(t1) <= thr2));
            if (__builtin_expect((int)amb_any, 0)) {  // rare exact path
                float q = __fdiv_rn(inter, u);
                if (fabsf(t1) <= thr2) hit = hit || (q >= c);
                if (fabsf(d) <= thr)
                    better = (q > __fdiv_rn(bi[g], bu[g]));
            }
            if (better) { bi[g] = inter; bu[g] = u; bidx[g] = base + t; }
        }

        unsigned bal = __ballot_sync(0xFFFFFFFFu, hit);  // OR over all 128 gts
        float res = bal ? -2.0f : -1.0f;
        if ((t & 31) == lane) myres = res;               // coalesced store staging
        if ((t & 31) == 31)  assign[base + (t & ~31) + lane] = myres;
    }

    // Epilogue: rounded quotient key (matches reference iou values exactly);
    // tie-break favors lowest anchor index = argmax first-occurrence.
    #pragma unroll
    for (int g = 0; g < 4; ++g) {
        int j = lane + 32 * g;
        float iou = __fdiv_rn(bi[g], bu[g]);
        unsigned long long key =
            ((unsigned long long)__float_as_uint(iou) << 32) |
            (unsigned)(0xFFFFFFFFu - (unsigned)bidx[g]);
        g_scratch[(size_t)gwarp * N_GT + j] = key;
    }
}

// Per-gt global max over warp candidates; gt claims its best anchor.
// Output is float32: positive floats are int-bit monotonic, and any float id
// (>= 0.0f) has larger int bits than -1.0f/-2.0f, so int atomicMax reproduces
// the reference's .at[col_arg].max(gt_id) overwrite semantics.
__global__ __launch_bounds__(256) void reduce_cols(float* __restrict__ assign,
                                                   int nwarps, int n)
{
    const int j   = blockIdx.x;       // one block per gt
    const int tid = threadIdx.x;

    unsigned long long best = 0;
    for (int k = tid; k < nwarps; k += 256) {
        unsigned long long v = g_scratch[(size_t)k * N_GT + j];
        if (v > best) best = v;
    }
    #pragma unroll
    for (int o = 16; o; o >>= 1) {
        unsigned long long v = __shfl_down_sync(0xFFFFFFFFu, best, o);
        if (v > best) best = v;
    }
    __shared__ unsigned long long s[8];
    if ((tid & 31) == 0) s[tid >> 5] = best;
    __syncthreads();
    if (tid < 32) {
        best = (tid < 8) ? s[tid] : 0ull;
        #pragma unroll
        for (int o = 4; o; o >>= 1) {
            unsigned long long v = __shfl_down_sync(0xFFFFFFFFu, best, o);
            if (v > best) best = v;
        }
        if (tid == 0) {
            unsigned idx = 0xFFFFFFFFu - (unsigned)(best & 0xFFFFFFFFull);
            if (idx < (unsigned)n)
                atomicMax((int*)assign + idx, __float_as_int((float)j));
        }
    }
}

extern "C" void kernel_launch(void* const* d_in, const int* in_sizes, int n_in,
                              void* d_out, int out_size) {
    // Robust to metadata order: anchor is the (much) larger input.
    int ia = (n_in >= 2 && in_sizes[1] > in_sizes[0]) ? 1 : 0;
    const float4* anchor = (const float4*)d_in[ia];       // [N,4] f32
    const float4* gt     = (const float4*)d_in[1 - ia];   // [128,4] f32
    float* assign = (float*)d_out;                        // __output__ float32

    int n = in_sizes[ia] / 4;                 // 262144
    int nwarps = n / CHUNK;                   // 4096
    int blocks = (nwarps + WARPS_PER_BLK - 1) / WARPS_PER_BLK;  // 512

    assign_main<<<blocks, THREADS>>>(anchor, gt, assign);
    reduce_cols<<<N_GT, 256>>>(assign, nwarps, n);
    (void)out_size;
}